// round 16
// baseline (speedup 1.0000x reference)
#include <cuda_runtime.h>
#include <cstdint>
#include <math.h>

// ---------------------------------------------------------------------------
// PerturbedSelect (verified R2-R15, rel_err 0.0 at R15):
//   bits[i] = o0^o1 of threefry2x32((0,42),(0,i))   [jax partitionable PRNG]
//   g = -log(-log(u(bits))) ; idx = argmax_d logits[k,d] + sigma*g
//   S[k,d] = count/1000 ; Y = X @ S^T
// R16: GEMM occupancy fix per R15 profile (occ=21% grid-limited, HBM 809GB/s
//      latency-bound): NSPLIT 8->16 => 1024 CTAs (~28 warps/SM). Argmax
//      frozen at R8 encoding (762us, alu-pipe bound, all rebalances failed).
// ---------------------------------------------------------------------------

#define NSAMP 1000
#define KOUT  64
#define DDIM  4096
#define BATCH 2048
#define NROWS (NSAMP * KOUT)          /* 64000 */
#define NSPLIT 16
#define DCHUNK (DDIM / NSPLIT)        /* 256 */

__device__ int      g_counts[KOUT * DDIM];     // zero-init; self-zeroing cycle
__device__ float    g_St[DDIM * KOUT];
__device__ float    g_Ypart[NSPLIT * BATCH * KOUT];
// Range atomics are idempotent across graph replays (same data -> same
// min/max), so static init is sufficient; no per-run reset.
__device__ uint32_t g_mn_u = 0xFFFFFFFFu;
__device__ uint32_t g_mx_u = 0u;

static __device__ __forceinline__ uint32_t enc_f(float x) {
    uint32_t u = __float_as_uint(x);
    return (u & 0x80000000u) ? ~u : (u | 0x80000000u);
}
static __device__ __forceinline__ float dec_f(uint32_t e) {
    uint32_t u = (e & 0x80000000u) ? (e ^ 0x80000000u) : ~e;
    return __uint_as_float(u);
}

static __device__ __forceinline__ uint32_t rotl32(uint32_t x, int d) {
    return __funnelshift_l(x, x, d);
}

// Threefry-2x32, 20 rounds, key (0, 42) — matches jax threefry2x32 lowering.
// Plain C++ / pure SHF rotations: the PROVEN fastest encoding (R8/R13).
static __device__ __forceinline__ void threefry(uint32_t x0, uint32_t x1,
                                                uint32_t& o0, uint32_t& o1) {
    const uint32_t k0 = 0u, k1 = 42u, k2 = 0u ^ 42u ^ 0x1BD11BDAu;
    x0 += k0; x1 += k1;
#define RND(r) { x0 += x1; x1 = rotl32(x1, r); x1 ^= x0; }
    RND(13) RND(15) RND(26) RND(6)
    x0 += k1; x1 += k2 + 1u;
    RND(17) RND(29) RND(16) RND(24)
    x0 += k2; x1 += k0 + 2u;
    RND(13) RND(15) RND(26) RND(6)
    x0 += k0; x1 += k1 + 3u;
    RND(17) RND(29) RND(16) RND(24)
    x0 += k1; x1 += k2 + 4u;
    RND(13) RND(15) RND(26) RND(6)
    x0 += k2; x1 += k0 + 5u;
#undef RND
    o0 = x0; o1 = x1;
}

// Exact jax gumbel from raw bits; double logs are correctly rounded and
// immune to --use_fast_math. Used ONLY for the rare candidates (~1-2/row).
static __device__ __forceinline__ float gumbel_f32(uint32_t bits) {
    const float tiny = 1.17549435082228751e-38f;
    float f = __uint_as_float((bits >> 9) | 0x3f800000u) - 1.0f;  // exact
    float u = fmaxf(tiny, __fadd_rn(f, tiny));
    float L1 = (float)log((double)u);
    float L2 = (float)log((double)(-L1));
    return -L2;
}

#define SIGMA_F ((float)(10.0 * 0.99998))

// ---------------------------------------------------------------- launch 1
// Logits min/max range. Idempotent across graph replays.
__global__ void range_kernel(const float* __restrict__ logits) {
    float mn = 3.4e38f, mx = -3.4e38f;
    for (int i = blockIdx.x * blockDim.x + threadIdx.x; i < KOUT * DDIM;
         i += gridDim.x * blockDim.x) {
        float v = logits[i];
        mn = fminf(mn, v); mx = fmaxf(mx, v);
    }
    for (int o = 16; o; o >>= 1) {
        mn = fminf(mn, __shfl_xor_sync(~0u, mn, o));
        mx = fmaxf(mx, __shfl_xor_sync(~0u, mx, o));
    }
    if ((threadIdx.x & 31) == 0) {
        atomicMin(&g_mn_u, enc_f(mn));
        atomicMax(&g_mx_u, enc_f(mx));
    }
}

// ---------------------------------------------------------------- launch 2
// One CTA per (sample,k) row. Pass 1: threefry all 4096 bits into registers,
// integer max over raw bits. Integer Bernoulli threshold (u^a >= 1-a(1-u),
// a = e^W >= 1, conservative) selects ~1-2 candidates/row for exact eval.
#define TPB 256
#define DPT (DDIM / TPB)   /* 16 */

__global__ __launch_bounds__(TPB) void argmax_kernel(const float* __restrict__ logits) {
    const int row = blockIdx.x;
    const int k = row & (KOUT - 1);
    const uint32_t base = (uint32_t)row * (uint32_t)DDIM;   // < 2^32
    const int t = threadIdx.x;

    uint32_t m[DPT];
#pragma unroll
    for (int j = 0; j < DPT; j++) {
        uint32_t i = base + (uint32_t)t * DPT + j;
        uint32_t o0, o1;
        threefry(0u, i, o0, o1);
        m[j] = o0 ^ o1;                 // raw 32-bit; order == (m>>9) order
    }

    // per-thread tree max (kept for the pass-2 guard)
    uint32_t r8[8];
#pragma unroll
    for (int j = 0; j < 8; j++) r8[j] = max(m[j], m[j + 8]);
#pragma unroll
    for (int j = 0; j < 4; j++) r8[j] = max(r8[j], r8[j + 4]);
    const uint32_t tmax = max(max(r8[0], r8[1]), max(r8[2], r8[3]));

    uint32_t wmax = tmax;
    for (int o = 16; o; o >>= 1) wmax = max(wmax, __shfl_xor_sync(~0u, wmax, o));

    __shared__ uint32_t swm[TPB / 32];
    __shared__ uint32_t s_E;
    __shared__ unsigned long long s_best;
    if ((t & 31) == 0) swm[t >> 5] = wmax;
    if (t == 0) {
        s_best = 0ull;
        // threshold scale, 2 MUFU per CTA, hidden under the barrier below
        float W = (dec_f(g_mx_u) - dec_f(g_mn_u)) * (1.0f / SIGMA_F) + 2e-3f;
        s_E = (uint32_t)(__expf(W) * 65536.0f) + 16u;   // >= exp(W)*2^16
    }
    __syncthreads();

    // CTA max + integer threshold, computed redundantly by every thread.
    uint32_t mmax = swm[0];
#pragma unroll
    for (int w = 1; w < TPB / 32; w++) mmax = max(mmax, swm[w]);
    const uint32_t mm9 = mmax >> 9;
    // u^a >= 1 - a(1-u) for a>=1: threshold sits BELOW the true window edge.
    uint32_t red = (uint32_t)(((unsigned long long)s_E *
                               (unsigned long long)(0x800000u - mm9)) >> 16);
    int mt = 0x800000 - (int)red - 256;     // 256-tick extra slack
    if (mt < 0) mt = 0;
    const uint32_t mt9 = (uint32_t)mt << 9; // <= mmax: >=1 candidate per row

    unsigned long long best = 0ull;
    if (tmax >= mt9) {                      // rare: ~1-2 threads per row
#pragma unroll
        for (int j = 0; j < DPT; j++) {
            if (m[j] >= mt9) {
                uint32_t d = (uint32_t)t * DPT + j;
                float g = gumbel_f32(m[j]);
                // z exactly as XLA: separate f32 mul + add (no FMA contraction)
                float z = __fadd_rn(logits[k * DDIM + (int)d], __fmul_rn(SIGMA_F, g));
                uint32_t oz = __float_as_uint(z);
                oz = (oz & 0x80000000u) ? ~oz : (oz | 0x80000000u);
                unsigned long long key =
                    ((unsigned long long)oz << 32) | (uint32_t)(0xFFFFFFFFu - d);
                best = max(best, key);      // tie -> lowest index wins
            }
        }
    }
    for (int o = 16; o; o >>= 1) best = max(best, __shfl_xor_sync(~0u, best, o));
    if ((t & 31) == 0 && best) atomicMax(&s_best, best);
    __syncthreads();
    if (t == 0) {
        int d = (int)(0xFFFFFFFFu - (uint32_t)(s_best & 0xFFFFFFFFu));
        atomicAdd(&g_counts[(k << 12) + d], 1);
    }
}

// ---------------------------------------------------------------- launch 3
// Transpose counts -> St AND reset counts to zero for the next graph replay
// (static zero-init covers the first run; every replay leaves counts == 0).
__global__ void build_st_kernel() {
    int i = blockIdx.x * blockDim.x + threadIdx.x;   // i = k*4096 + d
    int k = i >> 12, d = i & (DDIM - 1);
    int c = g_counts[i];
    g_St[d * KOUT + k] = (float)c * 0.001f;
    if (c) g_counts[i] = 0;
}

// ---------------------------------------------------------------- launch 4
// Partial GEMM: Ypart[s] = X[:, s-chunk] @ St[s-chunk].
// grid (BATCH/32, 16) = 1024 CTAs, 128 threads, 4x4 thread tile:
// per dd: 4 scalar LDS + 1 LDS.128 -> 16 FFMA.
#define TB_M 32
#define DC   64

__global__ __launch_bounds__(128) void gemm_partial_kernel(const float* __restrict__ X) {
    __shared__ float Xs[TB_M][DC + 4];
    __shared__ float Ss[DC][KOUT + 4];
    const int t = threadIdx.x;
    const int brow0 = blockIdx.x * TB_M;
    const int s = blockIdx.y;
    const int tr = t >> 4;          // 0..7  -> rows tr*4 .. tr*4+3
    const int tk = t & 15;          // 0..15 -> cols tk*4 .. tk*4+3
    float acc[4][4] = {};

    for (int d0 = s * DCHUNK; d0 < (s + 1) * DCHUNK; d0 += DC) {
#pragma unroll
        for (int l = 0; l < 4; l++) {       // 32*64 floats = 512 float4
            int v = t + l * 128;
            float4 x = *(const float4*)&X[(brow0 + (v >> 4)) * DDIM + d0 + (v & 15) * 4];
            *(float4*)&Xs[v >> 4][(v & 15) * 4] = x;
        }
#pragma unroll
        for (int l = 0; l < 8; l++) {       // 64*64 floats = 1024 float4
            int v = t + l * 128;
            float4 w = *(const float4*)&g_St[(d0 + (v >> 4)) * KOUT + (v & 15) * 4];
            *(float4*)&Ss[v >> 4][(v & 15) * 4] = w;
        }
        __syncthreads();
#pragma unroll
        for (int dd = 0; dd < DC; dd++) {
            float4 w = *(const float4*)&Ss[dd][tk * 4];
            float x0 = Xs[tr * 4 + 0][dd];
            float x1 = Xs[tr * 4 + 1][dd];
            float x2 = Xs[tr * 4 + 2][dd];
            float x3 = Xs[tr * 4 + 3][dd];
            acc[0][0] += x0 * w.x; acc[0][1] += x0 * w.y;
            acc[0][2] += x0 * w.z; acc[0][3] += x0 * w.w;
            acc[1][0] += x1 * w.x; acc[1][1] += x1 * w.y;
            acc[1][2] += x1 * w.z; acc[1][3] += x1 * w.w;
            acc[2][0] += x2 * w.x; acc[2][1] += x2 * w.y;
            acc[2][2] += x2 * w.z; acc[2][3] += x2 * w.w;
            acc[3][0] += x3 * w.x; acc[3][1] += x3 * w.y;
            acc[3][2] += x3 * w.z; acc[3][3] += x3 * w.w;
        }
        __syncthreads();
    }
#pragma unroll
    for (int r = 0; r < 4; r++)
#pragma unroll
        for (int c = 0; c < 4; c++)
            g_Ypart[(s * BATCH + brow0 + tr * 4 + r) * KOUT + tk * 4 + c] = acc[r][c];
}

// ---------------------------------------------------------------- launch 5
// Deterministic fixed-order reduction of the 16 partials.
__global__ void reduce_y_kernel(float* __restrict__ Y) {
    int i = blockIdx.x * blockDim.x + threadIdx.x;
    if (i < BATCH * KOUT) {
        const int N = BATCH * KOUT;
        float v = g_Ypart[i];
#pragma unroll
        for (int s = 1; s < NSPLIT; s++) v += g_Ypart[s * N + i];
        Y[i] = v;
    }
}

// ---------------------------------------------------------------------------
extern "C" void kernel_launch(void* const* d_in, const int* in_sizes, int n_in,
                              void* d_out, int out_size) {
    const float* X = (const float*)d_in[0];
    const float* logits = (const float*)d_in[1];
    if (n_in >= 2 && in_sizes[0] == KOUT * DDIM) {   // defensive: swapped order
        X = (const float*)d_in[1];
        logits = (const float*)d_in[0];
    }
    float* Y = (float*)d_out;

    range_kernel<<<64, 256>>>(logits);                       // 1
    argmax_kernel<<<NROWS, TPB>>>(logits);                   // 2
    build_st_kernel<<<1024, 256>>>();                        // 3
    {
        dim3 grid(BATCH / TB_M, NSPLIT);
        gemm_partial_kernel<<<grid, 128>>>(X);               // 4  <- ncu slot
    }
    reduce_y_kernel<<<(BATCH * KOUT + 255) / 256, 256>>>(Y); // 5
}

// round 17
// speedup vs baseline: 1.0020x; 1.0020x over previous
#include <cuda_runtime.h>
#include <cstdint>
#include <math.h>

// ---------------------------------------------------------------------------
// PerturbedSelect (verified R2-R16, rel_err ~2e-7):
//   bits[i] = o0^o1 of threefry2x32((0,42),(0,i))   [jax partitionable PRNG]
//   g = -log(-log(u(bits))) ; idx = argmax_d logits[k,d] + sigma*g
//   S[k,d] = count/1000 ; Y = X @ S^T
// R17: GEMM inner loop vectorized on BOTH operands per R16 profile
//      (L1=62.6% smem-port bound, fma=33%): dd steps by 4, LDS.128 for the
//      4 X rows and 4 Ss rows -> 8 LDS per 64 FFMA (was 20 per 64).
//      Argmax frozen at R8 encoding.
// ---------------------------------------------------------------------------

#define NSAMP 1000
#define KOUT  64
#define DDIM  4096
#define BATCH 2048
#define NROWS (NSAMP * KOUT)          /* 64000 */
#define NSPLIT 16
#define DCHUNK (DDIM / NSPLIT)        /* 256 */

__device__ int      g_counts[KOUT * DDIM];     // zero-init; self-zeroing cycle
__device__ float    g_St[DDIM * KOUT];
__device__ float    g_Ypart[NSPLIT * BATCH * KOUT];
// Range atomics are idempotent across graph replays (same data -> same
// min/max), so static init is sufficient; no per-run reset.
__device__ uint32_t g_mn_u = 0xFFFFFFFFu;
__device__ uint32_t g_mx_u = 0u;

static __device__ __forceinline__ uint32_t enc_f(float x) {
    uint32_t u = __float_as_uint(x);
    return (u & 0x80000000u) ? ~u : (u | 0x80000000u);
}
static __device__ __forceinline__ float dec_f(uint32_t e) {
    uint32_t u = (e & 0x80000000u) ? (e ^ 0x80000000u) : ~e;
    return __uint_as_float(u);
}

static __device__ __forceinline__ uint32_t rotl32(uint32_t x, int d) {
    return __funnelshift_l(x, x, d);
}

// Threefry-2x32, 20 rounds, key (0, 42) — matches jax threefry2x32 lowering.
// Plain C++ / pure SHF rotations: the PROVEN fastest encoding (R8/R13).
static __device__ __forceinline__ void threefry(uint32_t x0, uint32_t x1,
                                                uint32_t& o0, uint32_t& o1) {
    const uint32_t k0 = 0u, k1 = 42u, k2 = 0u ^ 42u ^ 0x1BD11BDAu;
    x0 += k0; x1 += k1;
#define RND(r) { x0 += x1; x1 = rotl32(x1, r); x1 ^= x0; }
    RND(13) RND(15) RND(26) RND(6)
    x0 += k1; x1 += k2 + 1u;
    RND(17) RND(29) RND(16) RND(24)
    x0 += k2; x1 += k0 + 2u;
    RND(13) RND(15) RND(26) RND(6)
    x0 += k0; x1 += k1 + 3u;
    RND(17) RND(29) RND(16) RND(24)
    x0 += k1; x1 += k2 + 4u;
    RND(13) RND(15) RND(26) RND(6)
    x0 += k2; x1 += k0 + 5u;
#undef RND
    o0 = x0; o1 = x1;
}

// Exact jax gumbel from raw bits; double logs are correctly rounded and
// immune to --use_fast_math. Used ONLY for the rare candidates (~1-2/row).
static __device__ __forceinline__ float gumbel_f32(uint32_t bits) {
    const float tiny = 1.17549435082228751e-38f;
    float f = __uint_as_float((bits >> 9) | 0x3f800000u) - 1.0f;  // exact
    float u = fmaxf(tiny, __fadd_rn(f, tiny));
    float L1 = (float)log((double)u);
    float L2 = (float)log((double)(-L1));
    return -L2;
}

#define SIGMA_F ((float)(10.0 * 0.99998))

// ---------------------------------------------------------------- launch 1
// Logits min/max range. Idempotent across graph replays.
__global__ void range_kernel(const float* __restrict__ logits) {
    float mn = 3.4e38f, mx = -3.4e38f;
    for (int i = blockIdx.x * blockDim.x + threadIdx.x; i < KOUT * DDIM;
         i += gridDim.x * blockDim.x) {
        float v = logits[i];
        mn = fminf(mn, v); mx = fmaxf(mx, v);
    }
    for (int o = 16; o; o >>= 1) {
        mn = fminf(mn, __shfl_xor_sync(~0u, mn, o));
        mx = fmaxf(mx, __shfl_xor_sync(~0u, mx, o));
    }
    if ((threadIdx.x & 31) == 0) {
        atomicMin(&g_mn_u, enc_f(mn));
        atomicMax(&g_mx_u, enc_f(mx));
    }
}

// ---------------------------------------------------------------- launch 2
// One CTA per (sample,k) row. Pass 1: threefry all 4096 bits into registers,
// integer max over raw bits. Integer Bernoulli threshold (u^a >= 1-a(1-u),
// a = e^W >= 1, conservative) selects ~1-2 candidates/row for exact eval.
#define TPB 256
#define DPT (DDIM / TPB)   /* 16 */

__global__ __launch_bounds__(TPB) void argmax_kernel(const float* __restrict__ logits) {
    const int row = blockIdx.x;
    const int k = row & (KOUT - 1);
    const uint32_t base = (uint32_t)row * (uint32_t)DDIM;   // < 2^32
    const int t = threadIdx.x;

    uint32_t m[DPT];
#pragma unroll
    for (int j = 0; j < DPT; j++) {
        uint32_t i = base + (uint32_t)t * DPT + j;
        uint32_t o0, o1;
        threefry(0u, i, o0, o1);
        m[j] = o0 ^ o1;                 // raw 32-bit; order == (m>>9) order
    }

    // per-thread tree max (kept for the pass-2 guard)
    uint32_t r8[8];
#pragma unroll
    for (int j = 0; j < 8; j++) r8[j] = max(m[j], m[j + 8]);
#pragma unroll
    for (int j = 0; j < 4; j++) r8[j] = max(r8[j], r8[j + 4]);
    const uint32_t tmax = max(max(r8[0], r8[1]), max(r8[2], r8[3]));

    uint32_t wmax = tmax;
    for (int o = 16; o; o >>= 1) wmax = max(wmax, __shfl_xor_sync(~0u, wmax, o));

    __shared__ uint32_t swm[TPB / 32];
    __shared__ uint32_t s_E;
    __shared__ unsigned long long s_best;
    if ((t & 31) == 0) swm[t >> 5] = wmax;
    if (t == 0) {
        s_best = 0ull;
        // threshold scale, 2 MUFU per CTA, hidden under the barrier below
        float W = (dec_f(g_mx_u) - dec_f(g_mn_u)) * (1.0f / SIGMA_F) + 2e-3f;
        s_E = (uint32_t)(__expf(W) * 65536.0f) + 16u;   // >= exp(W)*2^16
    }
    __syncthreads();

    // CTA max + integer threshold, computed redundantly by every thread.
    uint32_t mmax = swm[0];
#pragma unroll
    for (int w = 1; w < TPB / 32; w++) mmax = max(mmax, swm[w]);
    const uint32_t mm9 = mmax >> 9;
    // u^a >= 1 - a(1-u) for a>=1: threshold sits BELOW the true window edge.
    uint32_t red = (uint32_t)(((unsigned long long)s_E *
                               (unsigned long long)(0x800000u - mm9)) >> 16);
    int mt = 0x800000 - (int)red - 256;     // 256-tick extra slack
    if (mt < 0) mt = 0;
    const uint32_t mt9 = (uint32_t)mt << 9; // <= mmax: >=1 candidate per row

    unsigned long long best = 0ull;
    if (tmax >= mt9) {                      // rare: ~1-2 threads per row
#pragma unroll
        for (int j = 0; j < DPT; j++) {
            if (m[j] >= mt9) {
                uint32_t d = (uint32_t)t * DPT + j;
                float g = gumbel_f32(m[j]);
                // z exactly as XLA: separate f32 mul + add (no FMA contraction)
                float z = __fadd_rn(logits[k * DDIM + (int)d], __fmul_rn(SIGMA_F, g));
                uint32_t oz = __float_as_uint(z);
                oz = (oz & 0x80000000u) ? ~oz : (oz | 0x80000000u);
                unsigned long long key =
                    ((unsigned long long)oz << 32) | (uint32_t)(0xFFFFFFFFu - d);
                best = max(best, key);      // tie -> lowest index wins
            }
        }
    }
    for (int o = 16; o; o >>= 1) best = max(best, __shfl_xor_sync(~0u, best, o));
    if ((t & 31) == 0 && best) atomicMax(&s_best, best);
    __syncthreads();
    if (t == 0) {
        int d = (int)(0xFFFFFFFFu - (uint32_t)(s_best & 0xFFFFFFFFu));
        atomicAdd(&g_counts[(k << 12) + d], 1);
    }
}

// ---------------------------------------------------------------- launch 3
// Transpose counts -> St AND reset counts to zero for the next graph replay
// (static zero-init covers the first run; every replay leaves counts == 0).
__global__ void build_st_kernel() {
    int i = blockIdx.x * blockDim.x + threadIdx.x;   // i = k*4096 + d
    int k = i >> 12, d = i & (DDIM - 1);
    int c = g_counts[i];
    g_St[d * KOUT + k] = (float)c * 0.001f;
    if (c) g_counts[i] = 0;
}

// ---------------------------------------------------------------- launch 4
// Partial GEMM: Ypart[s] = X[:, s-chunk] @ St[s-chunk].
// grid (BATCH/32, 16) = 1024 CTAs, 128 threads, 4x4 thread tile.
// Inner loop steps dd by 4: 4 LDS.128 (X rows) + 4 LDS.128 (Ss rows)
// per 64 FFMA (was 20 LDS per 64).
#define TB_M 32
#define DC   64

__global__ __launch_bounds__(128) void gemm_partial_kernel(const float* __restrict__ X) {
    __shared__ float Xs[TB_M][DC + 4];     // row stride 68 floats = 17*16B
    __shared__ float Ss[DC][KOUT + 4];
    const int t = threadIdx.x;
    const int brow0 = blockIdx.x * TB_M;
    const int s = blockIdx.y;
    const int tr = t >> 4;          // 0..7  -> rows tr*4 .. tr*4+3
    const int tk = t & 15;          // 0..15 -> cols tk*4 .. tk*4+3
    float acc[4][4] = {};

    for (int d0 = s * DCHUNK; d0 < (s + 1) * DCHUNK; d0 += DC) {
#pragma unroll
        for (int l = 0; l < 4; l++) {       // 32*64 floats = 512 float4
            int v = t + l * 128;
            float4 x = *(const float4*)&X[(brow0 + (v >> 4)) * DDIM + d0 + (v & 15) * 4];
            *(float4*)&Xs[v >> 4][(v & 15) * 4] = x;
        }
#pragma unroll
        for (int l = 0; l < 8; l++) {       // 64*64 floats = 1024 float4
            int v = t + l * 128;
            float4 w = *(const float4*)&g_St[(d0 + (v >> 4)) * KOUT + (v & 15) * 4];
            *(float4*)&Ss[v >> 4][(v & 15) * 4] = w;
        }
        __syncthreads();
#pragma unroll
        for (int dd = 0; dd < DC; dd += 4) {
            float4 xv[4], wv[4];
#pragma unroll
            for (int r = 0; r < 4; r++)
                xv[r] = *(const float4*)&Xs[tr * 4 + r][dd];
#pragma unroll
            for (int q = 0; q < 4; q++)
                wv[q] = *(const float4*)&Ss[dd + q][tk * 4];
#pragma unroll
            for (int r = 0; r < 4; r++) {
                acc[r][0] += xv[r].x * wv[0].x; acc[r][1] += xv[r].x * wv[0].y;
                acc[r][2] += xv[r].x * wv[0].z; acc[r][3] += xv[r].x * wv[0].w;
                acc[r][0] += xv[r].y * wv[1].x; acc[r][1] += xv[r].y * wv[1].y;
                acc[r][2] += xv[r].y * wv[1].z; acc[r][3] += xv[r].y * wv[1].w;
                acc[r][0] += xv[r].z * wv[2].x; acc[r][1] += xv[r].z * wv[2].y;
                acc[r][2] += xv[r].z * wv[2].z; acc[r][3] += xv[r].z * wv[2].w;
                acc[r][0] += xv[r].w * wv[3].x; acc[r][1] += xv[r].w * wv[3].y;
                acc[r][2] += xv[r].w * wv[3].z; acc[r][3] += xv[r].w * wv[3].w;
            }
        }
        __syncthreads();
    }
#pragma unroll
    for (int r = 0; r < 4; r++)
#pragma unroll
        for (int c = 0; c < 4; c++)
            g_Ypart[(s * BATCH + brow0 + tr * 4 + r) * KOUT + tk * 4 + c] = acc[r][c];
}

// ---------------------------------------------------------------- launch 5
// Deterministic fixed-order reduction of the 16 partials.
__global__ void reduce_y_kernel(float* __restrict__ Y) {
    int i = blockIdx.x * blockDim.x + threadIdx.x;
    if (i < BATCH * KOUT) {
        const int N = BATCH * KOUT;
        float v = g_Ypart[i];
#pragma unroll
        for (int s = 1; s < NSPLIT; s++) v += g_Ypart[s * N + i];
        Y[i] = v;
    }
}

// ---------------------------------------------------------------------------
extern "C" void kernel_launch(void* const* d_in, const int* in_sizes, int n_in,
                              void* d_out, int out_size) {
    const float* X = (const float*)d_in[0];
    const float* logits = (const float*)d_in[1];
    if (n_in >= 2 && in_sizes[0] == KOUT * DDIM) {   // defensive: swapped order
        X = (const float*)d_in[1];
        logits = (const float*)d_in[0];
    }
    float* Y = (float*)d_out;

    range_kernel<<<64, 256>>>(logits);                       // 1
    argmax_kernel<<<NROWS, TPB>>>(logits);                   // 2
    build_st_kernel<<<1024, 256>>>();                        // 3
    {
        dim3 grid(BATCH / TB_M, NSPLIT);
        gemm_partial_kernel<<<grid, 128>>>(X);               // 4  <- ncu slot
    }
    reduce_y_kernel<<<(BATCH * KOUT + 255) / 256, 256>>>(Y); // 5
}